// round 1
// baseline (speedup 1.0000x reference)
#include <cuda_runtime.h>
#include <math_constants.h>

// Attention: B=256,H=16,Nq=Nk=49,D=64, fp32. One CTA per (b,h).
// Phase 1: S^T[k][q] = scale * Q.K^T  (4x4 register tiles, transposed smem operands)
// Softmax per q-column (1/(l+1e-9) folded into epilogue scale), V load overlapped.
// Phase 2: O = P.V (4x4 register tiles).

namespace {
constexpr int kNQ  = 49;
constexpr int kNK  = 49;
constexpr int kD   = 64;
constexpr int kPAD = 52;               // padded row count (mult of 4, decent bank spread)
constexpr float kScale = 0.125f;       // 1/sqrt(64)
constexpr float kEps   = 1e-9f;
}

__global__ __launch_bounds__(256)
void attn49_kernel(const float* __restrict__ gq,
                   const float* __restrict__ gk,
                   const float* __restrict__ gv,
                   float* __restrict__ gout)
{
    // sBuf holds Q^T (phase 1) then V row-major (phase 2). 64*52 >= 49*64.
    __shared__ __align__(16) float sBuf[kD * kPAD];
    __shared__ __align__(16) float sKT [kD * kPAD];
    __shared__ __align__(16) float sST [kPAD * kPAD];   // e[k][q] after softmax
    __shared__ float sLinv[kPAD];

    const int tid = threadIdx.x;
    const size_t base = (size_t)blockIdx.x * (kNQ * kD);
    const float* Q = gq + base;
    const float* K = gk + base;
    const float* V = gv + base;
    float* O = gout + base;

    // ---- Load Q, K transposed into smem: s[d][row] ----
    for (int idx = tid; idx < kNQ * kD; idx += 256) {
        const int r = idx >> 6;          // row (query/key index)
        const int c = idx & 63;          // dim
        sBuf[c * kPAD + r] = Q[idx];
        sKT [c * kPAD + r] = K[idx];
    }
    // zero the pad columns 49..51 (read by edge tiles)
    for (int idx = tid; idx < kD * (kPAD - kNQ); idx += 256) {
        const int j = idx / (kPAD - kNQ);
        const int c = kNQ + idx % (kPAD - kNQ);
        sBuf[j * kPAD + c] = 0.0f;
        sKT [j * kPAD + c] = 0.0f;
    }
    __syncthreads();

    // ---- Phase 1: scores, 4q x 4k per thread, store S^T[k][q] ----
    if (tid < 169) {                      // 13 x 13 tiles cover 52 x 52
        const int qt = (tid % 13) * 4;
        const int kt = (tid / 13) * 4;
        float acc[4][4];
        #pragma unroll
        for (int a = 0; a < 4; a++)
            #pragma unroll
            for (int b = 0; b < 4; b++) acc[a][b] = 0.0f;

        #pragma unroll 4
        for (int j = 0; j < kD; j++) {
            const float4 q4 = *(const float4*)(sBuf + j * kPAD + qt);
            const float4 k4 = *(const float4*)(sKT  + j * kPAD + kt);
            const float qa[4] = {q4.x, q4.y, q4.z, q4.w};
            const float ka[4] = {k4.x, k4.y, k4.z, k4.w};
            #pragma unroll
            for (int a = 0; a < 4; a++)
                #pragma unroll
                for (int b = 0; b < 4; b++)
                    acc[a][b] = fmaf(qa[a], ka[b], acc[a][b]);
        }
        #pragma unroll
        for (int b = 0; b < 4; b++)
            #pragma unroll
            for (int a = 0; a < 4; a++)
                sST[(kt + b) * kPAD + (qt + a)] = acc[a][b] * kScale;
    }
    __syncthreads();

    // ---- Softmax per q column (threads 0..51); V load (threads 64..255) ----
    if (tid < kPAD) {
        const int qc = tid;
        if (qc < kNQ) {
            float m = -CUDART_INF_F;
            for (int kk = 0; kk < kNK; kk++)
                m = fmaxf(m, sST[kk * kPAD + qc]);
            float l = 0.0f;
            for (int kk = 0; kk < kNK; kk++) {
                const float e = __expf(sST[kk * kPAD + qc] - m);
                sST[kk * kPAD + qc] = e;
                l += e;
            }
            sLinv[qc] = 1.0f / (l + kEps);
        } else {
            // pad columns: zero so phase-2 edge tiles accumulate zeros
            for (int kk = 0; kk < kNK; kk++) sST[kk * kPAD + qc] = 0.0f;
            sLinv[qc] = 0.0f;
        }
    } else if (tid >= 64) {
        // overwrite Q^T buffer with V, row-major [k][d], float4s
        const float4* V4 = (const float4*)V;
        float4* B4 = (float4*)sBuf;
        for (int idx = tid - 64; idx < (kNK * kD) / 4; idx += 192)
            B4[idx] = V4[idx];
    }
    __syncthreads();

    // ---- Phase 2: O[q][d] = linv[q] * sum_k e[k][q] * V[k][d], 4q x 4d per thread ----
    if (tid < 208) {                      // 13 q-tiles x 16 d-tiles
        const int dt = (tid & 15) * 4;
        const int qt = (tid >> 4) * 4;
        float acc[4][4];
        #pragma unroll
        for (int a = 0; a < 4; a++)
            #pragma unroll
            for (int b = 0; b < 4; b++) acc[a][b] = 0.0f;

        #pragma unroll 7
        for (int kk = 0; kk < kNK; kk++) {
            const float4 e4 = *(const float4*)(sST  + kk * kPAD + qt);
            const float4 v4 = *(const float4*)(sBuf + kk * kD   + dt);
            const float ea[4] = {e4.x, e4.y, e4.z, e4.w};
            const float va[4] = {v4.x, v4.y, v4.z, v4.w};
            #pragma unroll
            for (int a = 0; a < 4; a++)
                #pragma unroll
                for (int b = 0; b < 4; b++)
                    acc[a][b] = fmaf(ea[a], va[b], acc[a][b]);
        }
        #pragma unroll
        for (int a = 0; a < 4; a++) {
            const int qi = qt + a;
            if (qi < kNQ) {
                const float li = sLinv[qi];
                float4 o;
                o.x = acc[a][0] * li;
                o.y = acc[a][1] * li;
                o.z = acc[a][2] * li;
                o.w = acc[a][3] * li;
                *(float4*)(O + qi * kD + dt) = o;
            }
        }
    }
}

extern "C" void kernel_launch(void* const* d_in, const int* in_sizes, int n_in,
                              void* d_out, int out_size)
{
    const float* q = (const float*)d_in[0];
    const float* k = (const float*)d_in[1];
    const float* v = (const float*)d_in[2];
    float* out = (float*)d_out;

    const int bh = in_sizes[0] / (kNQ * kD);   // 256*16 = 4096
    attn49_kernel<<<bh, 256>>>(q, k, v, out);
}

// round 2
// speedup vs baseline: 1.3193x; 1.3193x over previous
#include <cuda_runtime.h>
#include <cuda_bf16.h>
#include <math_constants.h>
#include <cstdint>

// Attention B=256,H=16,Nq=Nk=49,D=64 fp32, one CTA per (b,h).
// Both GEMMs on tensor cores via bf16 hi/lo split (3-term), fp32 accum.
// Phase1: S^T = K.Q^T (row.col mma, plain ldmatrix operands)
// Phase2: O = P.V   (A=P via ldmatrix.trans on P^T, B=V via ldmatrix.trans)

namespace {
constexpr int kNQ = 49, kNK = 49, kD = 64;
constexpr int kP  = 72;                 // bf16 operand pitch (144B: odd multiple of 16B)
constexpr int kPS = 66;                 // fp32 score pitch
constexpr float kScale = 0.125f;        // 1/sqrt(64), folded into Q at load
constexpr float kEps   = 1e-9f;
constexpr int OPELEMS = 64 * kP;        // 4608 bf16 per operand array
constexpr int SMEM_BYTES = 4 * OPELEMS * 2 + 64 * kPS * 4 + 64 * 4;  // 54016
}

__device__ __forceinline__ uint32_t cvta_s(const void* p) {
    return (uint32_t)__cvta_generic_to_shared(p);
}
__device__ __forceinline__ void ldsm4(uint32_t& r0, uint32_t& r1, uint32_t& r2, uint32_t& r3, uint32_t a) {
    asm volatile("ldmatrix.sync.aligned.m8n8.x4.shared.b16 {%0,%1,%2,%3}, [%4];\n"
                 : "=r"(r0), "=r"(r1), "=r"(r2), "=r"(r3) : "r"(a));
}
__device__ __forceinline__ void ldsm4t(uint32_t& r0, uint32_t& r1, uint32_t& r2, uint32_t& r3, uint32_t a) {
    asm volatile("ldmatrix.sync.aligned.m8n8.x4.trans.shared.b16 {%0,%1,%2,%3}, [%4];\n"
                 : "=r"(r0), "=r"(r1), "=r"(r2), "=r"(r3) : "r"(a));
}
__device__ __forceinline__ void mma16816(float* c,
                                         uint32_t a0, uint32_t a1, uint32_t a2, uint32_t a3,
                                         uint32_t b0, uint32_t b1) {
    asm volatile("mma.sync.aligned.m16n8k16.row.col.f32.bf16.bf16.f32 "
                 "{%0,%1,%2,%3}, {%4,%5,%6,%7}, {%8,%9}, {%0,%1,%2,%3};\n"
                 : "+f"(c[0]), "+f"(c[1]), "+f"(c[2]), "+f"(c[3])
                 : "r"(a0), "r"(a1), "r"(a2), "r"(a3), "r"(b0), "r"(b1));
}

__global__ __launch_bounds__(256)
void attn49_mma(const float* __restrict__ gq,
                const float* __restrict__ gk,
                const float* __restrict__ gv,
                float* __restrict__ gout)
{
    extern __shared__ char smem[];
    __nv_bfloat16* sKh = (__nv_bfloat16*)smem;      // K_hi  -> later V_hi
    __nv_bfloat16* sKl = sKh + OPELEMS;             // K_lo  -> later V_lo
    __nv_bfloat16* sQh = sKl + OPELEMS;             // Q_hi  -> later P^T_hi
    __nv_bfloat16* sQl = sQh + OPELEMS;             // Q_lo  -> later P^T_lo
    float* sS    = (float*)(sQl + OPELEMS);         // S^T [64][66] fp32
    float* sLinv = sS + 64 * kPS;

    const int tid  = threadIdx.x;
    const int w    = tid >> 5;
    const int lane = tid & 31;
    const int g    = lane >> 3;    // ldmatrix lane group
    const int lr   = lane & 7;

    const size_t base = (size_t)blockIdx.x * (kNQ * kD);
    const float2* Q2 = (const float2*)(gq + base);
    const float2* K2 = (const float2*)(gk + base);
    const float2* V2 = (const float2*)(gv + base);
    float* O = gout + base;

    const __nv_bfloat162 z2 = __float2bfloat162_rn(0.0f);
    __nv_bfloat162* Qh2 = (__nv_bfloat162*)sQh;
    __nv_bfloat162* Ql2 = (__nv_bfloat162*)sQl;
    __nv_bfloat162* Kh2 = (__nv_bfloat162*)sKh;
    __nv_bfloat162* Kl2 = (__nv_bfloat162*)sKl;

    // ---- Load + hi/lo split Q (scaled) and K; pitch 36 bf16x2 per row ----
    for (int idx = tid; idx < (kNQ * kD) / 2; idx += 256) {
        const int r = idx >> 5, c2 = idx & 31;
        float2 q = Q2[idx];
        q.x *= kScale; q.y *= kScale;
        const float2 k = K2[idx];
        const __nv_bfloat16 qhx = __float2bfloat16(q.x), qhy = __float2bfloat16(q.y);
        const __nv_bfloat16 qlx = __float2bfloat16(q.x - __bfloat162float(qhx));
        const __nv_bfloat16 qly = __float2bfloat16(q.y - __bfloat162float(qhy));
        const __nv_bfloat16 khx = __float2bfloat16(k.x), khy = __float2bfloat16(k.y);
        const __nv_bfloat16 klx = __float2bfloat16(k.x - __bfloat162float(khx));
        const __nv_bfloat16 kly = __float2bfloat16(k.y - __bfloat162float(khy));
        Qh2[r * 36 + c2] = __halves2bfloat162(qhx, qhy);
        Ql2[r * 36 + c2] = __halves2bfloat162(qlx, qly);
        Kh2[r * 36 + c2] = __halves2bfloat162(khx, khy);
        Kl2[r * 36 + c2] = __halves2bfloat162(klx, kly);
    }
    // zero pad rows 49..63 of all four operand arrays (cols 0..63 used by ldmatrix)
    for (int i = tid; i < 15 * 36; i += 256) {
        const int off = (49 + i / 36) * 36 + (i % 36);
        Qh2[off] = z2; Ql2[off] = z2; Kh2[off] = z2; Kl2[off] = z2;
    }
    __syncthreads();

    // ---- Phase 1: S^T[key][q] = K . Q^T  (8 warps: 4 m-tiles x 2 n-halves) ----
    {
        const int ktb = (w & 3) * 16;      // key rows (m)
        const int qb  = (w >> 2) * 32;     // q cols (n), 4 n-tiles of 8
        float acc[4][4];
        #pragma unroll
        for (int i = 0; i < 4; i++)
            #pragma unroll
            for (int j = 0; j < 4; j++) acc[i][j] = 0.0f;

        const uint32_t aKh = cvta_s(sKh), aKl = cvta_s(sKl);
        const uint32_t aQh = cvta_s(sQh), aQl = cvta_s(sQl);

        #pragma unroll
        for (int kc = 0; kc < 4; kc++) {
            const int d = kc * 16;
            const int ao = (ktb + lr + ((g & 1) << 3)) * kP + d + ((g >> 1) << 3);
            uint32_t ah0, ah1, ah2, ah3, al0, al1, al2, al3;
            ldsm4(ah0, ah1, ah2, ah3, aKh + ao * 2);
            ldsm4(al0, al1, al2, al3, aKl + ao * 2);
            #pragma unroll
            for (int nt2 = 0; nt2 < 2; nt2++) {
                const int bo = (qb + nt2 * 16 + lr + ((g & 1) << 3)) * kP + d + ((g >> 1) << 3);
                uint32_t bh0, bh1, bh2, bh3, bl0, bl1, bl2, bl3;
                ldsm4(bh0, bh1, bh2, bh3, aQh + bo * 2);
                ldsm4(bl0, bl1, bl2, bl3, aQl + bo * 2);
                mma16816(acc[2 * nt2],     ah0, ah1, ah2, ah3, bh0, bh2);
                mma16816(acc[2 * nt2 + 1], ah0, ah1, ah2, ah3, bh1, bh3);
                mma16816(acc[2 * nt2],     ah0, ah1, ah2, ah3, bl0, bl2);
                mma16816(acc[2 * nt2 + 1], ah0, ah1, ah2, ah3, bl1, bl3);
                mma16816(acc[2 * nt2],     al0, al1, al2, al3, bh0, bh2);
                mma16816(acc[2 * nt2 + 1], al0, al1, al2, al3, bh1, bh3);
            }
        }
        // store S^T fp32
        const int r0 = ktb + (lane >> 2);
        #pragma unroll
        for (int nt = 0; nt < 4; nt++) {
            const int col = qb + nt * 8 + 2 * (lane & 3);
            *(float2*)&sS[r0 * kPS + col]       = make_float2(acc[nt][0], acc[nt][1]);
            *(float2*)&sS[(r0 + 8) * kPS + col] = make_float2(acc[nt][2], acc[nt][3]);
        }
    }
    __syncthreads();

    // ---- Softmax per q column (warps 0-1) writing P^T hi/lo over Q buffers;
    //      warps 2-7 convert V into the K buffers concurrently ----
    if (tid < 64) {
        const int qc = tid;
        if (qc < kNQ) {
            float m = -CUDART_INF_F;
            for (int k = 0; k < kNK; k++) m = fmaxf(m, sS[k * kPS + qc]);
            float l = 0.0f;
            for (int k = 0; k < kNK; k++) {
                const float e = __expf(sS[k * kPS + qc] - m);
                l += e;
                const __nv_bfloat16 h = __float2bfloat16(e);
                sQh[k * kP + qc] = h;
                sQl[k * kP + qc] = __float2bfloat16(e - __bfloat162float(h));
            }
            const __nv_bfloat16 z = __float2bfloat16(0.0f);
            for (int k = kNK; k < 64; k++) { sQh[k * kP + qc] = z; sQl[k * kP + qc] = z; }
            sLinv[qc] = 1.0f / (l + kEps);
        } else {
            const __nv_bfloat16 z = __float2bfloat16(0.0f);
            for (int k = 0; k < 64; k++) { sQh[k * kP + qc] = z; sQl[k * kP + qc] = z; }
        }
    } else {
        for (int idx = tid - 64; idx < (kNK * kD) / 2; idx += 192) {
            const int r = idx >> 5, c2 = idx & 31;
            const float2 v = V2[idx];
            const __nv_bfloat16 vhx = __float2bfloat16(v.x), vhy = __float2bfloat16(v.y);
            const __nv_bfloat16 vlx = __float2bfloat16(v.x - __bfloat162float(vhx));
            const __nv_bfloat16 vly = __float2bfloat16(v.y - __bfloat162float(vhy));
            Kh2[r * 36 + c2] = __halves2bfloat162(vhx, vhy);   // V_hi
            Kl2[r * 36 + c2] = __halves2bfloat162(vlx, vly);   // V_lo
        }
        for (int i = tid - 64; i < 15 * 36; i += 192) {
            const int off = (49 + i / 36) * 36 + (i % 36);
            Kh2[off] = z2; Kl2[off] = z2;
        }
    }
    __syncthreads();

    // ---- Phase 2: O[q][d] = P.V  (A=P via trans-ldmatrix on P^T, B=V via trans) ----
    {
        const int qtb = (w & 3) * 16;     // q rows (m)
        const int db  = (w >> 2) * 32;    // d cols (n)
        float acc[4][4];
        #pragma unroll
        for (int i = 0; i < 4; i++)
            #pragma unroll
            for (int j = 0; j < 4; j++) acc[i][j] = 0.0f;

        const uint32_t aPh = cvta_s(sQh), aPl = cvta_s(sQl);
        const uint32_t aVh = cvta_s(sKh), aVl = cvta_s(sKl);

        #pragma unroll
        for (int kc = 0; kc < 4; kc++) {
            const int kk = kc * 16;
            const int ao = (kk + ((g >> 1) << 3) + lr) * kP + qtb + ((g & 1) << 3);
            uint32_t ah0, ah1, ah2, ah3, al0, al1, al2, al3;
            ldsm4t(ah0, ah1, ah2, ah3, aPh + ao * 2);
            ldsm4t(al0, al1, al2, al3, aPl + ao * 2);
            #pragma unroll
            for (int nt2 = 0; nt2 < 2; nt2++) {
                const int bo = (kk + ((g >> 1) << 3) + lr) * kP + db + nt2 * 16 + ((g & 1) << 3);
                uint32_t bh0, bh1, bh2, bh3, bl0, bl1, bl2, bl3;
                ldsm4t(bh0, bh1, bh2, bh3, aVh + bo * 2);
                ldsm4t(bl0, bl1, bl2, bl3, aVl + bo * 2);
                mma16816(acc[2 * nt2],     ah0, ah1, ah2, ah3, bh0, bh2);
                mma16816(acc[2 * nt2 + 1], ah0, ah1, ah2, ah3, bh1, bh3);
                mma16816(acc[2 * nt2],     ah0, ah1, ah2, ah3, bl0, bl2);
                mma16816(acc[2 * nt2 + 1], ah0, ah1, ah2, ah3, bl1, bl3);
                mma16816(acc[2 * nt2],     al0, al1, al2, al3, bh0, bh2);
                mma16816(acc[2 * nt2 + 1], al0, al1, al2, al3, bh1, bh3);
            }
        }

        // epilogue: scale by 1/(l+eps), store to gmem
        const int q0 = qtb + (lane >> 2);
        const int q1 = q0 + 8;
        const float li0 = (q0 < kNQ) ? sLinv[q0] : 0.0f;
        const float li1 = (q1 < kNQ) ? sLinv[q1] : 0.0f;
        #pragma unroll
        for (int nt = 0; nt < 4; nt++) {
            const int d = db + nt * 8 + 2 * (lane & 3);
            if (q0 < kNQ)
                *(float2*)(O + q0 * kD + d) = make_float2(acc[nt][0] * li0, acc[nt][1] * li0);
            if (q1 < kNQ)
                *(float2*)(O + q1 * kD + d) = make_float2(acc[nt][2] * li1, acc[nt][3] * li1);
        }
    }
}

extern "C" void kernel_launch(void* const* d_in, const int* in_sizes, int n_in,
                              void* d_out, int out_size)
{
    const float* q = (const float*)d_in[0];
    const float* k = (const float*)d_in[1];
    const float* v = (const float*)d_in[2];
    float* out = (float*)d_out;

    cudaFuncSetAttribute(attn49_mma, cudaFuncAttributeMaxDynamicSharedMemorySize, SMEM_BYTES);
    const int bh = in_sizes[0] / (kNQ * kD);   // 4096
    attn49_mma<<<bh, 256, SMEM_BYTES>>>(q, k, v, out);
}

// round 3
// speedup vs baseline: 1.3344x; 1.0114x over previous
#include <cuda_runtime.h>
#include <cuda_bf16.h>
#include <math_constants.h>
#include <cstdint>

// Attention B=256,H=16,Nq=Nk=49,D=64 fp32, one CTA per (b,h).
// bf16 hi/lo split (3-term) tensor-core GEMMs; softmax fully in registers
// (shuffle reductions + tiny smem partials), no fp32 score buffer.

namespace {
constexpr int kNQ = 49, kNK = 49, kD = 64;
constexpr int kP  = 72;                 // bf16 operand pitch (144B: odd multiple of 16B)
constexpr float kScale = 0.125f;        // 1/sqrt(64), folded into Q at load
constexpr float kEps   = 1e-9f;
constexpr int OPELEMS = 64 * kP;        // 4608 bf16 per operand array
// 4 operand arrays + sMax[4][64] + sSum[4][64]
constexpr int SMEM_BYTES = 4 * OPELEMS * 2 + 2 * 4 * 64 * 4;   // 38912
}

__device__ __forceinline__ uint32_t cvta_s(const void* p) {
    return (uint32_t)__cvta_generic_to_shared(p);
}
__device__ __forceinline__ void ldsm4(uint32_t& r0, uint32_t& r1, uint32_t& r2, uint32_t& r3, uint32_t a) {
    asm volatile("ldmatrix.sync.aligned.m8n8.x4.shared.b16 {%0,%1,%2,%3}, [%4];\n"
                 : "=r"(r0), "=r"(r1), "=r"(r2), "=r"(r3) : "r"(a));
}
__device__ __forceinline__ void ldsm4t(uint32_t& r0, uint32_t& r1, uint32_t& r2, uint32_t& r3, uint32_t a) {
    asm volatile("ldmatrix.sync.aligned.m8n8.x4.trans.shared.b16 {%0,%1,%2,%3}, [%4];\n"
                 : "=r"(r0), "=r"(r1), "=r"(r2), "=r"(r3) : "r"(a));
}
__device__ __forceinline__ void mma16816(float* c,
                                         uint32_t a0, uint32_t a1, uint32_t a2, uint32_t a3,
                                         uint32_t b0, uint32_t b1) {
    asm volatile("mma.sync.aligned.m16n8k16.row.col.f32.bf16.bf16.f32 "
                 "{%0,%1,%2,%3}, {%4,%5,%6,%7}, {%8,%9}, {%0,%1,%2,%3};\n"
                 : "+f"(c[0]), "+f"(c[1]), "+f"(c[2]), "+f"(c[3])
                 : "r"(a0), "r"(a1), "r"(a2), "r"(a3), "r"(b0), "r"(b1));
}

__global__ __launch_bounds__(256, 5)
void attn49_mma(const float* __restrict__ gq,
                const float* __restrict__ gk,
                const float* __restrict__ gv,
                float* __restrict__ gout)
{
    extern __shared__ char smem[];
    __nv_bfloat16* sKh = (__nv_bfloat16*)smem;      // K_hi -> V_hi
    __nv_bfloat16* sKl = sKh + OPELEMS;             // K_lo -> V_lo
    __nv_bfloat16* sQh = sKl + OPELEMS;             // Q_hi -> P^T_hi
    __nv_bfloat16* sQl = sQh + OPELEMS;             // Q_lo -> P^T_lo
    float* sMax = (float*)(sQl + OPELEMS);          // [4][64] per-ktb col max partials
    float* sSum = sMax + 4 * 64;                    // [4][64] per-ktb col sum partials

    const int tid  = threadIdx.x;
    const int w    = tid >> 5;
    const int lane = tid & 31;
    const int g    = lane >> 3;
    const int lr   = lane & 7;

    const size_t base = (size_t)blockIdx.x * (kNQ * kD);
    const float2* Q2 = (const float2*)(gq + base);
    const float2* K2 = (const float2*)(gk + base);
    const float2* V2 = (const float2*)(gv + base);
    float* O = gout + base;

    const __nv_bfloat162 z2 = __float2bfloat162_rn(0.0f);
    __nv_bfloat162* Qh2 = (__nv_bfloat162*)sQh;
    __nv_bfloat162* Ql2 = (__nv_bfloat162*)sQl;
    __nv_bfloat162* Kh2 = (__nv_bfloat162*)sKh;
    __nv_bfloat162* Kl2 = (__nv_bfloat162*)sKl;

    // ---- Load + hi/lo split Q (scaled) and K ----
    for (int idx = tid; idx < (kNQ * kD) / 2; idx += 256) {
        const int r = idx >> 5, c2 = idx & 31;
        float2 q = Q2[idx];
        q.x *= kScale; q.y *= kScale;
        const float2 k = K2[idx];
        const __nv_bfloat16 qhx = __float2bfloat16(q.x), qhy = __float2bfloat16(q.y);
        const __nv_bfloat16 qlx = __float2bfloat16(q.x - __bfloat162float(qhx));
        const __nv_bfloat16 qly = __float2bfloat16(q.y - __bfloat162float(qhy));
        const __nv_bfloat16 khx = __float2bfloat16(k.x), khy = __float2bfloat16(k.y);
        const __nv_bfloat16 klx = __float2bfloat16(k.x - __bfloat162float(khx));
        const __nv_bfloat16 kly = __float2bfloat16(k.y - __bfloat162float(khy));
        Qh2[r * 36 + c2] = __halves2bfloat162(qhx, qhy);
        Ql2[r * 36 + c2] = __halves2bfloat162(qlx, qly);
        Kh2[r * 36 + c2] = __halves2bfloat162(khx, khy);
        Kl2[r * 36 + c2] = __halves2bfloat162(klx, kly);
    }
    for (int i = tid; i < 15 * 36; i += 256) {
        const int off = (49 + i / 36) * 36 + (i % 36);
        Qh2[off] = z2; Ql2[off] = z2; Kh2[off] = z2; Kl2[off] = z2;
    }
    __syncthreads();

    const int ktb = (w & 3) * 16;      // this warp's key rows (m in phase1)
    const int qb  = (w >> 2) * 32;     // this warp's q cols (n in phase1)

    // ---- Phase 1: S^T[key][q] = K . Q^T ----
    float acc[4][4];
    #pragma unroll
    for (int i = 0; i < 4; i++)
        #pragma unroll
        for (int j = 0; j < 4; j++) acc[i][j] = 0.0f;
    {
        const uint32_t aKh = cvta_s(sKh), aKl = cvta_s(sKl);
        const uint32_t aQh = cvta_s(sQh), aQl = cvta_s(sQl);
        #pragma unroll
        for (int kc = 0; kc < 4; kc++) {
            const int d = kc * 16;
            const int ao = (ktb + lr + ((g & 1) << 3)) * kP + d + ((g >> 1) << 3);
            uint32_t ah0, ah1, ah2, ah3, al0, al1, al2, al3;
            ldsm4(ah0, ah1, ah2, ah3, aKh + ao * 2);
            ldsm4(al0, al1, al2, al3, aKl + ao * 2);
            #pragma unroll
            for (int nt2 = 0; nt2 < 2; nt2++) {
                const int bo = (qb + nt2 * 16 + lr + ((g & 1) << 3)) * kP + d + ((g >> 1) << 3);
                uint32_t bh0, bh1, bh2, bh3, bl0, bl1, bl2, bl3;
                ldsm4(bh0, bh1, bh2, bh3, aQh + bo * 2);
                ldsm4(bl0, bl1, bl2, bl3, aQl + bo * 2);
                mma16816(acc[2 * nt2],     ah0, ah1, ah2, ah3, bh0, bh2);
                mma16816(acc[2 * nt2 + 1], ah0, ah1, ah2, ah3, bh1, bh3);
                mma16816(acc[2 * nt2],     ah0, ah1, ah2, ah3, bl0, bl2);
                mma16816(acc[2 * nt2 + 1], ah0, ah1, ah2, ah3, bl1, bl3);
                mma16816(acc[2 * nt2],     al0, al1, al2, al3, bh0, bh2);
                mma16816(acc[2 * nt2 + 1], al0, al1, al2, al3, bh1, bh3);
            }
        }
    }

    // Fragment geometry: rows r0, r0+8 (k); cols c0=qb+nt*8+2*(lane&3), c0+1 (q)
    const int r0 = ktb + (lane >> 2);
    const bool v0 = (r0 < kNK);
    const bool v1 = (r0 + 8 < kNK);

    // ---- per-warp column max over k (shuffle across lane bits 2..4) ----
    float pm[4][2];
    #pragma unroll
    for (int nt = 0; nt < 4; nt++) {
        pm[nt][0] = fmaxf(v0 ? acc[nt][0] : -CUDART_INF_F, v1 ? acc[nt][2] : -CUDART_INF_F);
        pm[nt][1] = fmaxf(v0 ? acc[nt][1] : -CUDART_INF_F, v1 ? acc[nt][3] : -CUDART_INF_F);
    }
    #pragma unroll
    for (int off = 4; off <= 16; off <<= 1)
        #pragma unroll
        for (int nt = 0; nt < 4; nt++) {
            pm[nt][0] = fmaxf(pm[nt][0], __shfl_xor_sync(0xffffffffu, pm[nt][0], off));
            pm[nt][1] = fmaxf(pm[nt][1], __shfl_xor_sync(0xffffffffu, pm[nt][1], off));
        }
    if (lane < 4) {
        #pragma unroll
        for (int nt = 0; nt < 4; nt++)
            *(float2*)&sMax[(w & 3) * 64 + qb + nt * 8 + 2 * lane] = make_float2(pm[nt][0], pm[nt][1]);
    }
    __syncthreads();

    // ---- combine cross-warp max, exponentiate, reduce sums, write P^T bf16 ----
    {
        #pragma unroll
        for (int nt = 0; nt < 4; nt++) {
            const int c0 = qb + nt * 8 + 2 * (lane & 3);
            float2 m01 = *(const float2*)&sMax[0 * 64 + c0];
            #pragma unroll
            for (int p = 1; p < 4; p++) {
                const float2 t = *(const float2*)&sMax[p * 64 + c0];
                m01.x = fmaxf(m01.x, t.x);
                m01.y = fmaxf(m01.y, t.y);
            }
            acc[nt][0] = v0 ? __expf(acc[nt][0] - m01.x) : 0.0f;
            acc[nt][1] = v0 ? __expf(acc[nt][1] - m01.y) : 0.0f;
            acc[nt][2] = v1 ? __expf(acc[nt][2] - m01.x) : 0.0f;
            acc[nt][3] = v1 ? __expf(acc[nt][3] - m01.y) : 0.0f;
        }
        // column partial sums
        float ps[4][2];
        #pragma unroll
        for (int nt = 0; nt < 4; nt++) {
            ps[nt][0] = acc[nt][0] + acc[nt][2];
            ps[nt][1] = acc[nt][1] + acc[nt][3];
        }
        #pragma unroll
        for (int off = 4; off <= 16; off <<= 1)
            #pragma unroll
            for (int nt = 0; nt < 4; nt++) {
                ps[nt][0] += __shfl_xor_sync(0xffffffffu, ps[nt][0], off);
                ps[nt][1] += __shfl_xor_sync(0xffffffffu, ps[nt][1], off);
            }
        if (lane < 4) {
            #pragma unroll
            for (int nt = 0; nt < 4; nt++)
                *(float2*)&sSum[(w & 3) * 64 + qb + nt * 8 + 2 * lane] = make_float2(ps[nt][0], ps[nt][1]);
        }
        // write P^T hi/lo (bf16x2 per adjacent column pair)
        #pragma unroll
        for (int nt = 0; nt < 4; nt++) {
            const int c0 = qb + nt * 8 + 2 * (lane & 3);
            const __nv_bfloat16 h0 = __float2bfloat16(acc[nt][0]);
            const __nv_bfloat16 h1 = __float2bfloat16(acc[nt][1]);
            const __nv_bfloat16 h2 = __float2bfloat16(acc[nt][2]);
            const __nv_bfloat16 h3 = __float2bfloat16(acc[nt][3]);
            *(__nv_bfloat162*)&sQh[r0 * kP + c0]       = __halves2bfloat162(h0, h1);
            *(__nv_bfloat162*)&sQh[(r0 + 8) * kP + c0] = __halves2bfloat162(h2, h3);
            *(__nv_bfloat162*)&sQl[r0 * kP + c0] =
                __halves2bfloat162(__float2bfloat16(acc[nt][0] - __bfloat162float(h0)),
                                   __float2bfloat16(acc[nt][1] - __bfloat162float(h1)));
            *(__nv_bfloat162*)&sQl[(r0 + 8) * kP + c0] =
                __halves2bfloat162(__float2bfloat16(acc[nt][2] - __bfloat162float(h2)),
                                   __float2bfloat16(acc[nt][3] - __bfloat162float(h3)));
        }
    }

    // ---- V load + split into (dead) K buffers; all 256 threads ----
    for (int idx = tid; idx < (kNK * kD) / 2; idx += 256) {
        const int r = idx >> 5, c2 = idx & 31;
        const float2 v = V2[idx];
        const __nv_bfloat16 vhx = __float2bfloat16(v.x), vhy = __float2bfloat16(v.y);
        const __nv_bfloat16 vlx = __float2bfloat16(v.x - __bfloat162float(vhx));
        const __nv_bfloat16 vly = __float2bfloat16(v.y - __bfloat162float(vhy));
        Kh2[r * 36 + c2] = __halves2bfloat162(vhx, vhy);
        Kl2[r * 36 + c2] = __halves2bfloat162(vlx, vly);
    }
    for (int i = tid; i < 15 * 36; i += 256) {
        const int off = (49 + i / 36) * 36 + (i % 36);
        Kh2[off] = z2; Kl2[off] = z2;
    }
    __syncthreads();

    // ---- Phase 2: O = P.V ----
    {
        const int qtb = (w & 3) * 16;
        const int db  = (w >> 2) * 32;
        float oacc[4][4];
        #pragma unroll
        for (int i = 0; i < 4; i++)
            #pragma unroll
            for (int j = 0; j < 4; j++) oacc[i][j] = 0.0f;

        const uint32_t aPh = cvta_s(sQh), aPl = cvta_s(sQl);
        const uint32_t aVh = cvta_s(sKh), aVl = cvta_s(sKl);

        #pragma unroll
        for (int kc = 0; kc < 4; kc++) {
            const int kk = kc * 16;
            const int ao = (kk + ((g >> 1) << 3) + lr) * kP + qtb + ((g & 1) << 3);
            uint32_t ah0, ah1, ah2, ah3, al0, al1, al2, al3;
            ldsm4t(ah0, ah1, ah2, ah3, aPh + ao * 2);
            ldsm4t(al0, al1, al2, al3, aPl + ao * 2);
            #pragma unroll
            for (int nt2 = 0; nt2 < 2; nt2++) {
                const int bo = (kk + ((g >> 1) << 3) + lr) * kP + db + nt2 * 16 + ((g & 1) << 3);
                uint32_t bh0, bh1, bh2, bh3, bl0, bl1, bl2, bl3;
                ldsm4t(bh0, bh1, bh2, bh3, aVh + bo * 2);
                ldsm4t(bl0, bl1, bl2, bl3, aVl + bo * 2);
                mma16816(oacc[2 * nt2],     ah0, ah1, ah2, ah3, bh0, bh2);
                mma16816(oacc[2 * nt2 + 1], ah0, ah1, ah2, ah3, bh1, bh3);
                mma16816(oacc[2 * nt2],     ah0, ah1, ah2, ah3, bl0, bl2);
                mma16816(oacc[2 * nt2 + 1], ah0, ah1, ah2, ah3, bl1, bl3);
                mma16816(oacc[2 * nt2],     al0, al1, al2, al3, bh0, bh2);
                mma16816(oacc[2 * nt2 + 1], al0, al1, al2, al3, bh1, bh3);
            }
        }

        // epilogue: l = sum of 4 partials, scale by 1/(l+eps), store
        const int q0 = qtb + (lane >> 2);
        const int q1 = q0 + 8;
        float li0 = 0.0f, li1 = 0.0f;
        if (q0 < kNQ)
            li0 = 1.0f / (sSum[0 * 64 + q0] + sSum[1 * 64 + q0] +
                          sSum[2 * 64 + q0] + sSum[3 * 64 + q0] + kEps);
        if (q1 < kNQ)
            li1 = 1.0f / (sSum[0 * 64 + q1] + sSum[1 * 64 + q1] +
                          sSum[2 * 64 + q1] + sSum[3 * 64 + q1] + kEps);
        #pragma unroll
        for (int nt = 0; nt < 4; nt++) {
            const int d = db + nt * 8 + 2 * (lane & 3);
            if (q0 < kNQ)
                *(float2*)(O + q0 * kD + d) = make_float2(oacc[nt][0] * li0, oacc[nt][1] * li0);
            if (q1 < kNQ)
                *(float2*)(O + q1 * kD + d) = make_float2(oacc[nt][2] * li1, oacc[nt][3] * li1);
        }
    }
}

extern "C" void kernel_launch(void* const* d_in, const int* in_sizes, int n_in,
                              void* d_out, int out_size)
{
    const float* q = (const float*)d_in[0];
    const float* k = (const float*)d_in[1];
    const float* v = (const float*)d_in[2];
    float* out = (float*)d_out;

    const int bh = in_sizes[0] / (kNQ * kD);   // 4096
    attn49_mma<<<bh, 256, SMEM_BYTES>>>(q, k, v, out);
}